// round 17
// baseline (speedup 1.0000x reference)
#include <cuda_runtime.h>
#include <cuda_bf16.h>
#include <cstdint>

// Problem constants
#define BATCH 4
#define SEQ   2048
#define DM    1024
#define NH    16
#define HD    64
#define M_ROWS (BATCH*SEQ)   // 8192

// Scratch (device globals; no allocation allowed)
__device__ float g_qkv[(size_t)M_ROWS * 3 * DM];   // [B*T, 3*C] (sel, head, hd)
__device__ float g_y[(size_t)M_ROWS * DM];         // [B*T, C]

__device__ __forceinline__ uint32_t f2tf(float f) {
    uint32_t u;
    asm("cvt.rna.tf32.f32 %0, %1;" : "=r"(u) : "f"(f));
    return u;
}

__device__ __forceinline__ uint32_t smem_u32(const void* p) {
    uint32_t a;
    asm("{ .reg .u64 t; cvta.to.shared.u64 t, %1; cvt.u32.u64 %0, t; }"
        : "=r"(a) : "l"(p));
    return a;
}

#define MMA_TF32(acc, a, b0v, b1v)                                              \
    asm volatile(                                                               \
        "mma.sync.aligned.m16n8k8.row.col.f32.tf32.tf32.f32 "                   \
        "{%0,%1,%2,%3}, {%4,%5,%6,%7}, {%8,%9}, {%0,%1,%2,%3};"                 \
        : "+f"(acc[0]), "+f"(acc[1]), "+f"(acc[2]), "+f"(acc[3])                \
        : "r"(a[0]), "r"(a[1]), "r"(a[2]), "r"(a[3]), "r"(b0v), "r"(b1v))

// Variant taking 4 explicit A regs (for P-as-A-fragment renaming)
#define MMA_TF32_A4(acc, a0, a1, a2, a3, b0v, b1v)                              \
    asm volatile(                                                               \
        "mma.sync.aligned.m16n8k8.row.col.f32.tf32.tf32.f32 "                   \
        "{%0,%1,%2,%3}, {%4,%5,%6,%7}, {%8,%9}, {%0,%1,%2,%3};"                 \
        : "+f"(acc[0]), "+f"(acc[1]), "+f"(acc[2]), "+f"(acc[3])                \
        : "r"(a0), "r"(a1), "r"(a2), "r"(a3), "r"(b0v), "r"(b1v))

#define LDSM_X4(r, addr)                                                        \
    asm volatile(                                                               \
        "ldmatrix.sync.aligned.m8n8.x4.shared.b16 {%0,%1,%2,%3}, [%4];"         \
        : "=r"((r)[0]), "=r"((r)[1]), "=r"((r)[2]), "=r"((r)[3])                \
        : "r"(addr))

#define TFS 136   // B smem row stride (8 mod 32 -> conflict-free quad frag loads)
#define AST 20    // A smem row stride (16B aligned; LDSM bank-distinct)

// 0.125 * log2(e): QK^T logits produced directly in log2 domain
#define QSCALE 0.18033688011112042f

// Attention dynamic smem: ks[128][68] + vst[64][132]
#define KS_W   68
#define VST_W  132
#define ATT_SMEM ((128 * KS_W + 64 * VST_W) * 4)   // 68608 B

// ---------------------------------------------------------------------------
// TF32 GEMM with bias (r12/r15, measured best 415.7us): 128x128 tile, BK=16
// double-buffered, 128 thr (4 warps 2x2), warp tile 64x64, 2 CTAs/SM.
// A frags via ldmatrix.x4, B frags scalar (conflict-free). cvt at store.
// ---------------------------------------------------------------------------
__global__ __launch_bounds__(128, 2) void tf32_gemm_bias(
    const float* __restrict__ A, const float* __restrict__ B,
    const float* __restrict__ bias, float* __restrict__ C,
    int M, int N, int K)
{
    __shared__ uint32_t As[2][128][AST];   // [buf][row][k]  (10240 B per buf)
    __shared__ uint32_t Bs[2][16][TFS];    // [buf][k][col]

    const int tid  = threadIdx.x;
    const int lane = tid & 31;
    const int wid  = tid >> 5;
    const int gid  = lane >> 2;
    const int tig  = lane & 3;
    const int wm   = (wid & 1) * 64;
    const int wn   = (wid >> 1) * 64;
    const int bm   = blockIdx.y * 128;
    const int bn   = blockIdx.x * 128;

    const int br = tid >> 4;          // 0..7
    const int bc = (tid & 15) * 4;    // 0..60

    const float* Ap = A + (size_t)(bm + tid) * K;
    const float* Bp = B + (size_t)br * N + bn + bc;

    const uint32_t aLdsm = smem_u32(&As[0][0][0]) +
        (uint32_t)(((wm + (lane & 15)) * AST + ((lane >> 4) << 2)) * 4);

    float acc[4][8][4];
#pragma unroll
    for (int mt = 0; mt < 4; mt++)
#pragma unroll
        for (int nt = 0; nt < 8; nt++)
#pragma unroll
            for (int i = 0; i < 4; i++) acc[mt][nt][i] = 0.f;

    const int ntiles = K / 16;
    float4 pa[4], pb[4];

    // Preload tile 0 -> buf 0
    {
#pragma unroll
        for (int j = 0; j < 4; j++) pa[j] = ((const float4*)Ap)[j];
        pb[0] = *(const float4*)(Bp);
        pb[1] = *(const float4*)(Bp + 64);
        pb[2] = *(const float4*)(Bp + (size_t)8 * N);
        pb[3] = *(const float4*)(Bp + (size_t)8 * N + 64);
#pragma unroll
        for (int j = 0; j < 4; j++) {
            uint4 w;
            w.x = f2tf(pa[j].x); w.y = f2tf(pa[j].y);
            w.z = f2tf(pa[j].z); w.w = f2tf(pa[j].w);
            *(uint4*)&As[0][tid][j * 4] = w;
        }
        Bs[0][br][bc + 0]      = f2tf(pb[0].x);
        Bs[0][br][bc + 1]      = f2tf(pb[0].y);
        Bs[0][br][bc + 2]      = f2tf(pb[0].z);
        Bs[0][br][bc + 3]      = f2tf(pb[0].w);
        Bs[0][br][bc + 64]     = f2tf(pb[1].x);
        Bs[0][br][bc + 65]     = f2tf(pb[1].y);
        Bs[0][br][bc + 66]     = f2tf(pb[1].z);
        Bs[0][br][bc + 67]     = f2tf(pb[1].w);
        Bs[0][br + 8][bc + 0]  = f2tf(pb[2].x);
        Bs[0][br + 8][bc + 1]  = f2tf(pb[2].y);
        Bs[0][br + 8][bc + 2]  = f2tf(pb[2].z);
        Bs[0][br + 8][bc + 3]  = f2tf(pb[2].w);
        Bs[0][br + 8][bc + 64] = f2tf(pb[3].x);
        Bs[0][br + 8][bc + 65] = f2tf(pb[3].y);
        Bs[0][br + 8][bc + 66] = f2tf(pb[3].z);
        Bs[0][br + 8][bc + 67] = f2tf(pb[3].w);
    }
    __syncthreads();

    int buf = 0;
    for (int t = 0; t < ntiles; t++) {
        if (t + 1 < ntiles) {
            const int k0 = (t + 1) * 16;
            const float* ap = Ap + k0;
            const float* bp = Bp + (size_t)k0 * N;
#pragma unroll
            for (int j = 0; j < 4; j++) pa[j] = ((const float4*)ap)[j];
            pb[0] = *(const float4*)(bp);
            pb[1] = *(const float4*)(bp + 64);
            pb[2] = *(const float4*)(bp + (size_t)8 * N);
            pb[3] = *(const float4*)(bp + (size_t)8 * N + 64);
        }

        const uint32_t aBufAddr = aLdsm + (uint32_t)(buf * 10240);
#pragma unroll
        for (int kk = 0; kk < 16; kk += 8) {
            uint32_t af[4][4], bf[8][2];
            LDSM_X4(af[0], aBufAddr + kk * 4);
            LDSM_X4(af[1], aBufAddr + 1 * 1280 + kk * 4);
            LDSM_X4(af[2], aBufAddr + 2 * 1280 + kk * 4);
            LDSM_X4(af[3], aBufAddr + 3 * 1280 + kk * 4);
#pragma unroll
            for (int nt = 0; nt < 8; nt++) {
                const int c = wn + nt * 8 + gid;
                bf[nt][0] = Bs[buf][kk + tig][c];
                bf[nt][1] = Bs[buf][kk + tig + 4][c];
            }
#pragma unroll
            for (int mt = 0; mt < 4; mt++)
#pragma unroll
                for (int nt = 0; nt < 8; nt++)
                    MMA_TF32(acc[mt][nt], af[mt], bf[nt][0], bf[nt][1]);
        }

        if (t + 1 < ntiles) {
            const int nb = buf ^ 1;
#pragma unroll
            for (int j = 0; j < 4; j++) {
                uint4 w;
                w.x = f2tf(pa[j].x); w.y = f2tf(pa[j].y);
                w.z = f2tf(pa[j].z); w.w = f2tf(pa[j].w);
                *(uint4*)&As[nb][tid][j * 4] = w;
            }
            Bs[nb][br][bc + 0]      = f2tf(pb[0].x);
            Bs[nb][br][bc + 1]      = f2tf(pb[0].y);
            Bs[nb][br][bc + 2]      = f2tf(pb[0].z);
            Bs[nb][br][bc + 3]      = f2tf(pb[0].w);
            Bs[nb][br][bc + 64]     = f2tf(pb[1].x);
            Bs[nb][br][bc + 65]     = f2tf(pb[1].y);
            Bs[nb][br][bc + 66]     = f2tf(pb[1].z);
            Bs[nb][br][bc + 67]     = f2tf(pb[1].w);
            Bs[nb][br + 8][bc + 0]  = f2tf(pb[2].x);
            Bs[nb][br + 8][bc + 1]  = f2tf(pb[2].y);
            Bs[nb][br + 8][bc + 2]  = f2tf(pb[2].z);
            Bs[nb][br + 8][bc + 3]  = f2tf(pb[2].w);
            Bs[nb][br + 8][bc + 64] = f2tf(pb[3].x);
            Bs[nb][br + 8][bc + 65] = f2tf(pb[3].y);
            Bs[nb][br + 8][bc + 66] = f2tf(pb[3].z);
            Bs[nb][br + 8][bc + 67] = f2tf(pb[3].w);
        }
        __syncthreads();
        buf ^= 1;
    }

    // Epilogue with bias
#pragma unroll
    for (int mt = 0; mt < 4; mt++) {
        const int r0 = bm + wm + mt * 16 + gid;
#pragma unroll
        for (int nt = 0; nt < 8; nt++) {
            const int col = bn + wn + nt * 8 + 2 * tig;
            const float bx = bias[col], by = bias[col + 1];
            float2 v0 = {acc[mt][nt][0] + bx, acc[mt][nt][1] + by};
            float2 v1 = {acc[mt][nt][2] + bx, acc[mt][nt][3] + by};
            *(float2*)(C + (size_t)r0 * N + col)       = v0;
            *(float2*)(C + (size_t)(r0 + 8) * N + col) = v1;
        }
    }
}

// ---------------------------------------------------------------------------
// Tensor-core flash attention: 128-key super-tiles (barriers halved),
// key-permuted V (P as A-fragment), exp2-domain softmax.
// Precision: rna on Q, K, V, and P; l sums the ROUNDED p so the PV numerator
// and softmax denominator see identical values (rounding bias cancels).
// Dynamic smem: ks[128][68] + vst[64][132] = 68608 B.
// ---------------------------------------------------------------------------
__global__ __launch_bounds__(128) void flash_attn_tc(
    const float* __restrict__ qkv, float* __restrict__ y)
{
    extern __shared__ uint32_t dsm[];
    uint32_t (*ks)[KS_W]   = (uint32_t (*)[KS_W])dsm;             // [128][68]
    uint32_t (*vst)[VST_W] = (uint32_t (*)[VST_W])(dsm + 128 * KS_W); // [64][132]

    const int tid  = threadIdx.x;
    const int lane = tid & 31;
    const int wid  = tid >> 5;
    const int gid  = lane >> 2;
    const int tig  = lane & 3;
    const int wq   = wid * 32;
    const int qt0  = (int)(gridDim.x - 1 - blockIdx.x) * 128;  // heavy tiles first
    const int h    = blockIdx.y;
    const int b    = blockIdx.z;

    uint32_t qf[2][8][4];
#pragma unroll
    for (int mt = 0; mt < 2; mt++) {
        const float* q0 = qkv + ((size_t)(b * SEQ + qt0 + wq + mt * 16 + gid) * (3 * DM)) + h * HD;
        const float* q1 = q0 + (size_t)8 * 3 * DM;
#pragma unroll
        for (int kk = 0; kk < 8; kk++) {
            qf[mt][kk][0] = f2tf(q0[kk * 8 + tig]     * QSCALE);
            qf[mt][kk][1] = f2tf(q1[kk * 8 + tig]     * QSCALE);
            qf[mt][kk][2] = f2tf(q0[kk * 8 + tig + 4] * QSCALE);
            qf[mt][kk][3] = f2tf(q1[kk * 8 + tig + 4] * QSCALE);
        }
    }

    float o[2][8][4];
#pragma unroll
    for (int mt = 0; mt < 2; mt++)
#pragma unroll
        for (int nt = 0; nt < 8; nt++) {
            o[mt][nt][0] = 0.f; o[mt][nt][1] = 0.f;
            o[mt][nt][2] = 0.f; o[mt][nt][3] = 0.f;
        }
    float m[2][2] = {{-1e30f, -1e30f}, {-1e30f, -1e30f}};
    float l[2][2] = {{0.f, 0.f}, {0.f, 0.f}};

    // Loader mapping: thread t owns key row t of the 128-key super-tile
    const int krow  = tid;
    // V key-slot: sigma(k) = (k&120) | ((k&1)<<2) | ((k&7)>>1)
    const int kslot = (krow & 120) | ((krow & 1) << 2) | ((krow & 7) >> 1);

    const int nsuper = qt0 / 128 + 1;
    for (int st = 0; st < nsuper; st++) {
        const int kb0 = st * 128;

        __syncthreads();   // previous super-tile fully consumed
        {
            const float* kp = qkv + ((size_t)(b * SEQ + kb0 + krow) * (3 * DM)) + DM + h * HD;
            const float* vp = kp + DM;
#pragma unroll
            for (int j = 0; j < 64; j += 4) {
                float4 k4 = *(const float4*)(kp + j);
                float4 v4 = *(const float4*)(vp + j);
                uint4 w;
                w.x = f2tf(k4.x); w.y = f2tf(k4.y); w.z = f2tf(k4.z); w.w = f2tf(k4.w);
                *(uint4*)&ks[krow][j] = w;
                vst[j + 0][kslot] = f2tf(v4.x);
                vst[j + 1][kslot] = f2tf(v4.y);
                vst[j + 2][kslot] = f2tf(v4.z);
                vst[j + 3][kslot] = f2tf(v4.w);
            }
        }
        __syncthreads();

        // Two 64-key compute sub-passes over the loaded super-tile
#pragma unroll
        for (int kb = 0; kb < 2; kb++) {
            const int kt0 = kb0 + kb * 64;
            if (kt0 > qt0 + wq + 31) continue;   // whole warp masked
            const int ko = kb * 64;

            float acc[2][8][4];
#pragma unroll
            for (int mt = 0; mt < 2; mt++)
#pragma unroll
                for (int nt = 0; nt < 8; nt++) {
                    acc[mt][nt][0] = 0.f; acc[mt][nt][1] = 0.f;
                    acc[mt][nt][2] = 0.f; acc[mt][nt][3] = 0.f;
                }
#pragma unroll
            for (int kk = 0; kk < 8; kk++) {
                uint32_t bf0[8], bf1[8];
#pragma unroll
                for (int nt = 0; nt < 8; nt++) {
                    bf0[nt] = ks[ko + nt * 8 + gid][kk * 8 + tig];
                    bf1[nt] = ks[ko + nt * 8 + gid][kk * 8 + tig + 4];
                }
#pragma unroll
                for (int mt = 0; mt < 2; mt++)
#pragma unroll
                    for (int nt = 0; nt < 8; nt++)
                        MMA_TF32(acc[mt][nt], qf[mt][kk], bf0[nt], bf1[nt]);
            }

            // Causal mask
#pragma unroll
            for (int mt = 0; mt < 2; mt++) {
                if (kt0 + 63 > qt0 + wq + mt * 16) {
                    const int r0 = qt0 + wq + mt * 16 + gid, r1 = r0 + 8;
#pragma unroll
                    for (int nt = 0; nt < 8; nt++) {
                        const int c = kt0 + nt * 8 + 2 * tig;
                        if (c     > r0) acc[mt][nt][0] = -1e30f;
                        if (c + 1 > r0) acc[mt][nt][1] = -1e30f;
                        if (c     > r1) acc[mt][nt][2] = -1e30f;
                        if (c + 1 > r1) acc[mt][nt][3] = -1e30f;
                    }
                }
            }

            // Online softmax (log2 domain); P rounded to tf32 with rna and
            // l accumulates the ROUNDED p (numerator/denominator consistent)
#pragma unroll
            for (int mt = 0; mt < 2; mt++) {
                float mt0 = -1e30f, mt1 = -1e30f;
#pragma unroll
                for (int nt = 0; nt < 8; nt++) {
                    mt0 = fmaxf(mt0, fmaxf(acc[mt][nt][0], acc[mt][nt][1]));
                    mt1 = fmaxf(mt1, fmaxf(acc[mt][nt][2], acc[mt][nt][3]));
                }
                mt0 = fmaxf(mt0, __shfl_xor_sync(0xffffffffu, mt0, 1));
                mt0 = fmaxf(mt0, __shfl_xor_sync(0xffffffffu, mt0, 2));
                mt1 = fmaxf(mt1, __shfl_xor_sync(0xffffffffu, mt1, 1));
                mt1 = fmaxf(mt1, __shfl_xor_sync(0xffffffffu, mt1, 2));

                const float mn0 = fmaxf(m[mt][0], mt0), mn1 = fmaxf(m[mt][1], mt1);
                const float cr0 = exp2f(m[mt][0] - mn0), cr1 = exp2f(m[mt][1] - mn1);
                m[mt][0] = mn0; m[mt][1] = mn1;
                l[mt][0] *= cr0; l[mt][1] *= cr1;

                float s0 = 0.f, s1 = 0.f;
#pragma unroll
                for (int nt = 0; nt < 8; nt++) {
                    const float p0 = __uint_as_float(f2tf(exp2f(acc[mt][nt][0] - mn0)));
                    const float p1 = __uint_as_float(f2tf(exp2f(acc[mt][nt][1] - mn0)));
                    const float p2 = __uint_as_float(f2tf(exp2f(acc[mt][nt][2] - mn1)));
                    const float p3 = __uint_as_float(f2tf(exp2f(acc[mt][nt][3] - mn1)));
                    s0 += p0 + p1;
                    s1 += p2 + p3;
                    o[mt][nt][0] *= cr0; o[mt][nt][1] *= cr0;
                    o[mt][nt][2] *= cr1; o[mt][nt][3] *= cr1;
                    acc[mt][nt][0] = p0;
                    acc[mt][nt][1] = p1;
                    acc[mt][nt][2] = p2;
                    acc[mt][nt][3] = p3;
                }
                s0 += __shfl_xor_sync(0xffffffffu, s0, 1);
                s0 += __shfl_xor_sync(0xffffffffu, s0, 2);
                s1 += __shfl_xor_sync(0xffffffffu, s1, 1);
                s1 += __shfl_xor_sync(0xffffffffu, s1, 2);
                l[mt][0] += s0; l[mt][1] += s1;
            }

            // O += P V : P's C-layout regs as A-fragment under key-permuted V
#pragma unroll
            for (int kk = 0; kk < 8; kk++) {
#pragma unroll
                for (int nt = 0; nt < 8; nt++) {
                    const uint32_t b0 = vst[nt * 8 + gid][ko + kk * 8 + tig];
                    const uint32_t b1 = vst[nt * 8 + gid][ko + kk * 8 + tig + 4];
#pragma unroll
                    for (int mt = 0; mt < 2; mt++)
                        MMA_TF32_A4(o[mt][nt],
                                    __float_as_uint(acc[mt][kk][0]),
                                    __float_as_uint(acc[mt][kk][2]),
                                    __float_as_uint(acc[mt][kk][1]),
                                    __float_as_uint(acc[mt][kk][3]),
                                    b0, b1);
                }
            }
        }
    }

    // Epilogue: normalize and write y [B*T, DM]
#pragma unroll
    for (int mt = 0; mt < 2; mt++) {
        const float i0 = 1.f / l[mt][0], i1 = 1.f / l[mt][1];
        float* y0 = y + (size_t)(b * SEQ + qt0 + wq + mt * 16 + gid) * DM + h * HD;
        float* y1 = y0 + (size_t)8 * DM;
#pragma unroll
        for (int nt = 0; nt < 8; nt++) {
            const int c = nt * 8 + 2 * tig;
            float2 w0 = {o[mt][nt][0] * i0, o[mt][nt][1] * i0};
            float2 w1 = {o[mt][nt][2] * i1, o[mt][nt][3] * i1};
            *(float2*)(y0 + c) = w0;
            *(float2*)(y1 + c) = w1;
        }
    }
}

// ---------------------------------------------------------------------------
// Launch
// ---------------------------------------------------------------------------
extern "C" void kernel_launch(void* const* d_in, const int* in_sizes, int n_in,
                              void* d_out, int out_size)
{
    (void)in_sizes; (void)n_in; (void)out_size;
    const float* x      = (const float*)d_in[0];
    const float* w_qkv  = (const float*)d_in[1];
    const float* b_qkv  = (const float*)d_in[2];
    const float* w_proj = (const float*)d_in[3];
    const float* b_proj = (const float*)d_in[4];
    float* out = (float*)d_out;

    float* qkv = nullptr;
    float* y   = nullptr;
    cudaGetSymbolAddress((void**)&qkv, g_qkv);
    cudaGetSymbolAddress((void**)&y,   g_y);

    cudaFuncSetAttribute(flash_attn_tc,
                         cudaFuncAttributeMaxDynamicSharedMemorySize, ATT_SMEM);

    // 1) QKV projection: [8192,1024] @ [1024,3072] + b
    tf32_gemm_bias<<<dim3(3 * DM / 128, M_ROWS / 128), 128>>>(
        x, w_qkv, b_qkv, qkv, M_ROWS, 3 * DM, DM);

    // 2) Causal flash attention (128 q/block, 128-key super-tiles)
    flash_attn_tc<<<dim3(SEQ / 128, NH, BATCH), 128, ATT_SMEM>>>(qkv, y);

    // 3) Output projection: [8192,1024] @ [1024,1024] + b
    tf32_gemm_bias<<<dim3(DM / 128, M_ROWS / 128), 128>>>(
        y, w_proj, b_proj, out, M_ROWS, DM, DM);
}